// round 16
// baseline (speedup 1.0000x reference)
#include <cuda_runtime.h>
#include <cuda_fp16.h>
#include <math.h>
#include <stdint.h>

#define DD 512
#define SS 8192
#define BB 4
#define MM (BB * SS)
#define GN_EPS 1e-6f
#define ROPE_L2 0.20762050593045702   // log2(10000)/64

// CTA tile 128m x 256n, BK=32, pitch 80B rows. A(10240) B(20480)
#define SM_B  10240
#define STG1  30720
#define SMEM1 (3 * STG1)
#define NT 256

// ------------------------------------------------------------ device globals
__device__ __half g_XQs[(size_t)MM*DD];
__device__ __half g_XKs[(size_t)MM*DD];
__device__ __half g_Wqs[DD*DD], g_Wvs[DD*DD];
__device__ __half g_QTh[(size_t)DD*MM];
__device__ __half g_VTs[(size_t)DD*MM];
__device__ __half g_Kph[(size_t)MM*DD];
__device__ float  g_QtV[(size_t)BB*DD*DD];
__device__ __half g_QtVTs[(size_t)BB*DD*DD];

// ------------------------------------------------------------------ helpers
__device__ __forceinline__ uint32_t smem_u32(const void* p) {
    uint32_t a;
    asm("{ .reg .u64 t; cvta.to.shared.u64 t, %1; cvt.u32.u64 %0, t; }" : "=r"(a) : "l"(p));
    return a;
}
#define CPA(dst, src) \
    asm volatile("cp.async.cg.shared.global [%0], [%1], 16;" :: "r"(dst), "l"(src) : "memory")
#define CPA_COMMIT() asm volatile("cp.async.commit_group;" ::: "memory")
#define CPA_WAIT(n)  asm volatile("cp.async.wait_group %0;" :: "n"(n) : "memory")
#define LDSM4(R, a) \
    asm volatile("ldmatrix.sync.aligned.m8n8.x4.shared.b16 {%0,%1,%2,%3}, [%4];" \
        : "=r"((R)[0]), "=r"((R)[1]), "=r"((R)[2]), "=r"((R)[3]) : "r"(a))

__device__ __forceinline__ void mma16816(float* d, const uint32_t* a, const uint32_t* b) {
    asm volatile("mma.sync.aligned.m16n8k16.row.col.f32.f16.f16.f32 "
        "{%0,%1,%2,%3},{%4,%5,%6,%7},{%8,%9},{%0,%1,%2,%3};"
        : "+f"(d[0]), "+f"(d[1]), "+f"(d[2]), "+f"(d[3])
        : "r"(a[0]), "r"(a[1]), "r"(a[2]), "r"(a[3]), "r"(b[0]), "r"(b[1]));
}

__device__ __forceinline__ float silu_f(float x) { return x / (1.0f + __expf(-x)); }

// load one stage: A 128 rows, B 256 rows; 32 fp16/row (64B), pitch 80B.
// 256 threads x 6 cp.asyncs
__device__ __forceinline__ void load_stage(const __half* A, const __half* B,
                                           size_t pa, size_t pb,
                                           int ar0, int br0, int kelem,
                                           uint32_t smst, int tid) {
    const int row = tid >> 1;
    const int cpair = (tid & 1) * 2;
#pragma unroll
    for (int i = 0; i < 2; i++) {
        const int c = cpair + i;
        const char* sA  = (const char*)(A + (size_t)(ar0 + row) * pa + kelem) + c * 16;
        const char* sB0 = (const char*)(B + (size_t)(br0 + row) * pb + kelem) + c * 16;
        const char* sB1 = (const char*)(B + (size_t)(br0 + row + 128) * pb + kelem) + c * 16;
        CPA(smst + row * 80 + c * 16, sA);
        CPA(smst + SM_B + row * 80 + c * 16, sB0);
        CPA(smst + SM_B + (row + 128) * 80 + c * 16, sB1);
    }
}

// one BK=32 stage: warp tile 64m x 64n, single-term fp16
__device__ __forceinline__ void mma_stage(uint32_t smst, int wm, int wn, int lane,
                                          float acc[4][8][4]) {
#pragma unroll
    for (int kk = 0; kk < 2; kk++) {
        uint32_t a_addr = smst + (uint32_t)((wm * 64 + (lane & 15)) * 80 + kk * 32 + (lane >> 4) * 16);
        uint32_t ah[4][4];
        LDSM4(ah[0], a_addr);
        LDSM4(ah[1], a_addr + 16 * 80);
        LDSM4(ah[2], a_addr + 32 * 80);
        LDSM4(ah[3], a_addr + 48 * 80);
        uint32_t b_addr = smst + SM_B +
            (uint32_t)((wn * 64 + ((lane >> 4) << 3) + (lane & 7)) * 80 + kk * 32 + ((lane >> 3) & 1) * 16);
#pragma unroll
        for (int np = 0; np < 4; np++) {
            uint32_t bf[4];
            LDSM4(bf, b_addr + np * 16 * 80);
#pragma unroll
            for (int half = 0; half < 2; half++)
#pragma unroll
                for (int mi = 0; mi < 4; mi++)
                    mma16816(acc[mi][np * 2 + half], ah[mi], bf + half * 2);
        }
    }
}

__device__ __forceinline__ void run_gemm(const __half* A, const __half* B,
                                         size_t pa, size_t pb,
                                         int ar0, int br0, int kbase, int nstages,
                                         float acc[4][8][4], char* sm, int tid) {
#pragma unroll
    for (int mi = 0; mi < 4; mi++)
#pragma unroll
        for (int ni = 0; ni < 8; ni++)
#pragma unroll
            for (int j = 0; j < 4; j++) acc[mi][ni][j] = 0.f;

    uint32_t smb = smem_u32(sm);
    const int wid = tid >> 5;
    const int wm = wid >> 2, wn = wid & 3, lane = tid & 31;

    load_stage(A, B, pa, pb, ar0, br0, kbase, smb, tid);
    CPA_COMMIT();
    load_stage(A, B, pa, pb, ar0, br0, kbase + 32, smb + STG1, tid);
    CPA_COMMIT();

    for (int s = 0; s < nstages; s++) {
        if (s + 1 < nstages) { CPA_WAIT(1); } else { CPA_WAIT(0); }
        __syncthreads();
        if (s + 2 < nstages) {
            load_stage(A, B, pa, pb, ar0, br0, kbase + (s + 2) * 32,
                       smb + ((s + 2) % 3) * STG1, tid);
            CPA_COMMIT();
        }
        mma_stage(smb + (s % 3) * STG1, wm, wn, lane, acc);
    }
}

// =======================================================================
// GEMM1: Y = X@W^T + bias, rope(first 64 ch), silu.
// IS_Q: write QTh (transposed).  else: VTs (pre-rope) + Kph (row-major)
// grid (2, 256), 256 threads
// =======================================================================
template<bool IS_Q>
__global__ __launch_bounds__(NT) void k_gemm1(
    const __half* __restrict__ Xs, const __half* __restrict__ Ws,
    const float* __restrict__ bias)
{
    extern __shared__ char sm[];
    const int tid = threadIdx.x;
    const int row0 = blockIdx.y * 128, col0 = blockIdx.x * 256;
    float acc[4][8][4];
    run_gemm(Xs, Ws, DD, DD, row0, col0, 0, DD / 32, acc, sm, tid);

    const int lane = tid & 31, wid = tid >> 5;
    const int wm = wid >> 2, wn = wid & 3;
    const int cb = col0 + wn * 64 + (lane & 3) * 2;
    float b0[8], b1[8];
#pragma unroll
    for (int ni = 0; ni < 8; ni++) { b0[ni] = bias[cb + ni * 8]; b1[ni] = bias[cb + ni * 8 + 1]; }
    const bool ropew = (cb < 64);
    float invf[8];
    if (ropew) {
#pragma unroll
        for (int ni = 0; ni < 8; ni++)
            invf[ni] = (float)exp2(-(double)(cb + ni * 8) * ROPE_L2);
    }

#pragma unroll
    for (int mi = 0; mi < 4; mi++)
#pragma unroll
    for (int h = 0; h < 2; h++) {
        const int r = row0 + wm * 64 + mi * 16 + (lane >> 2) + h * 8;
        const float pos = (float)(r & (SS - 1));
#pragma unroll
        for (int ni = 0; ni < 8; ni++) {
            const int c = cb + ni * 8;
            float y0 = acc[mi][ni][h * 2 + 0] + b0[ni];
            float y1 = acc[mi][ni][h * 2 + 1] + b1[ni];
            if (!IS_Q) {   // V = silu(pre-rope), single fp16
                g_VTs[(size_t)c * MM + r]       = __float2half_rn(silu_f(y0));
                g_VTs[(size_t)(c + 1) * MM + r] = __float2half_rn(silu_f(y1));
            }
            if (ropew) {
                float sv, cv;
                sincosf(pos * invf[ni], &sv, &cv);
                float t0 = y0 * cv - y1 * sv;
                float t1 = y1 * cv + y0 * sv;
                y0 = t0; y1 = t1;
            }
            const __half s0 = __float2half_rn(silu_f(y0));
            const __half s1 = __float2half_rn(silu_f(y1));
            if (IS_Q) {
                g_QTh[(size_t)c * MM + r]       = s0;
                g_QTh[(size_t)(c + 1) * MM + r] = s1;
            } else {
                *(__half2*)&g_Kph[(size_t)r * DD + c] = __halves2half2(s0, s1);
            }
        }
    }
}

// =======================================================================
// GEMM2: QtV[b][d][e] += sum_n QTh[d][n] * VTs[e][n]; split-K 16 x 512
// grid (2, 4, 64), 256 threads
// =======================================================================
__global__ __launch_bounds__(NT) void k_gemm2()
{
    extern __shared__ char sm[];
    const int tid = threadIdx.x;
    const int e0 = blockIdx.x * 256, d0 = blockIdx.y * 128;
    const int b = blockIdx.z >> 4, sp = blockIdx.z & 15;
    const int nbase = b * SS + sp * 512;
    float acc[4][8][4];
    run_gemm(g_QTh, g_VTs, MM, MM, d0, e0, nbase, 512 / 32, acc, sm, tid);

    const int lane = tid & 31, wid = tid >> 5;
    const int wm = wid >> 2, wn = wid & 3;
    const int cb = e0 + wn * 64 + (lane & 3) * 2;
    float* base = g_QtV + (size_t)b * DD * DD;
#pragma unroll
    for (int mi = 0; mi < 4; mi++)
#pragma unroll
    for (int h = 0; h < 2; h++) {
        const int d = d0 + wm * 64 + mi * 16 + (lane >> 2) + h * 8;
#pragma unroll
        for (int ni = 0; ni < 8; ni++) {
            const int e = cb + ni * 8;
            atomicAdd(base + (size_t)d * DD + e,     acc[mi][ni][h * 2 + 0]);
            atomicAdd(base + (size_t)d * DD + e + 1, acc[mi][ni][h * 2 + 1]);
        }
    }
}

// =======================================================================
// GEMM3 + GroupNorm: out[r][e] = GN( sum_d Kph[r][d] * QtVTs[e][d] )
// grid (2, 256), 256 threads; warp owns exactly one 64-ch group
// =======================================================================
__global__ __launch_bounds__(NT) void k_gemm3(
    const float* __restrict__ gn_w, const float* __restrict__ gn_b,
    float* __restrict__ out)
{
    extern __shared__ char sm[];
    const int tid = threadIdx.x;
    const int row0 = blockIdx.y * 128, e0 = blockIdx.x * 256;
    const int b = row0 >> 13;
    float acc[4][8][4];
    run_gemm(g_Kph, g_QtVTs + (size_t)b * DD * DD, DD, DD, row0, e0, 0, DD / 32, acc, sm, tid);

    const int lane = tid & 31, wid = tid >> 5;
    const int wm = wid >> 2, wn = wid & 3;
    const int cb = e0 + wn * 64 + (lane & 3) * 2;

#pragma unroll
    for (int mi = 0; mi < 4; mi++)
#pragma unroll
    for (int h = 0; h < 2; h++) {
        const int r = row0 + wm * 64 + mi * 16 + (lane >> 2) + h * 8;
        float s = 0.f, q = 0.f;
#pragma unroll
        for (int ni = 0; ni < 8; ni++) {
            float v0 = acc[mi][ni][h * 2 + 0], v1 = acc[mi][ni][h * 2 + 1];
            s += v0 + v1;
            q += v0 * v0 + v1 * v1;
        }
        s += __shfl_xor_sync(0xffffffffu, s, 1);
        q += __shfl_xor_sync(0xffffffffu, q, 1);
        s += __shfl_xor_sync(0xffffffffu, s, 2);
        q += __shfl_xor_sync(0xffffffffu, q, 2);
        const float mean = s * (1.0f / 64.0f);
        const float var  = q * (1.0f / 64.0f) - mean * mean;
        const float rstd = rsqrtf(var + GN_EPS);
        float* orow = out + (size_t)r * DD;
#pragma unroll
        for (int ni = 0; ni < 8; ni++) {
            const int e = cb + ni * 8;
            float2 o;
            o.x = (acc[mi][ni][h * 2 + 0] - mean) * rstd * gn_w[e]     + gn_b[e];
            o.y = (acc[mi][ni][h * 2 + 1] - mean) * rstd * gn_w[e + 1] + gn_b[e + 1];
            *(float2*)(orow + e) = o;
        }
    }
}

// ---------------------------------------------------------- aux kernels
__global__ void k_round2(const float* __restrict__ srcA, const float* __restrict__ srcB,
                         __half* __restrict__ dA, __half* __restrict__ dB)
{
    const float* src = blockIdx.y ? srcB : srcA;
    __half* dst = blockIdx.y ? dB : dA;
    const int i = blockIdx.x * 256 + threadIdx.x;
    float4 v = ((const float4*)src)[i];
    ((__half2*)dst)[i * 2]     = __halves2half2(__float2half_rn(v.x), __float2half_rn(v.y));
    ((__half2*)dst)[i * 2 + 1] = __halves2half2(__float2half_rn(v.z), __float2half_rn(v.w));
}

__global__ void k_zero_qtv() {
    int idx = blockIdx.x * 256 + threadIdx.x;
    ((float4*)g_QtV)[idx] = make_float4(0.f, 0.f, 0.f, 0.f);
}

// transpose + round QtV -> QtVTs (single fp16).  grid (16,16,4), block (32,8)
__global__ void k_trans() {
    __shared__ float t[32][33];
    const int b = blockIdx.z;
    const int d0 = blockIdx.y * 32, e0 = blockIdx.x * 32;
    const float* src = g_QtV + (size_t)b * DD * DD;
    __half* ds = g_QtVTs + (size_t)b * DD * DD;
    const int x = threadIdx.x, y0 = threadIdx.y;
#pragma unroll
    for (int i = 0; i < 32; i += 8)
        t[y0 + i][x] = src[(size_t)(d0 + y0 + i) * DD + e0 + x];
    __syncthreads();
#pragma unroll
    for (int i = 0; i < 32; i += 8)
        ds[(size_t)(e0 + y0 + i) * DD + d0 + x] = __float2half_rn(t[x][y0 + i]);
}

__global__ void k_tail(const float* __restrict__ sh, const float* __restrict__ sc,
                       float* __restrict__ out, int out_size) {
    out[out_size - 2] = sh[0];
    out[out_size - 1] = sc[0];
}

// ---------------------------------------------------------------- launch
extern "C" void kernel_launch(void* const* d_in, const int* in_sizes, int n_in,
                              void* d_out, int out_size)
{
    (void)in_sizes; (void)n_in;
    const float* X_Q  = (const float*)d_in[0];
    const float* X_KV = (const float*)d_in[1];
    const float* S_h  = (const float*)d_in[2];
    const float* S_C  = (const float*)d_in[3];
    const float* Wq   = (const float*)d_in[4];
    const float* bq   = (const float*)d_in[5];
    const float* Wv   = (const float*)d_in[8];
    const float* bv   = (const float*)d_in[9];
    const float* gn_w = (const float*)d_in[10];
    const float* gn_b = (const float*)d_in[11];
    float* out = (float*)d_out;

    static bool attr_done = false;
    if (!attr_done) {
        cudaFuncSetAttribute(k_gemm1<true>,  cudaFuncAttributeMaxDynamicSharedMemorySize, SMEM1);
        cudaFuncSetAttribute(k_gemm1<false>, cudaFuncAttributeMaxDynamicSharedMemorySize, SMEM1);
        cudaFuncSetAttribute(k_gemm2, cudaFuncAttributeMaxDynamicSharedMemorySize, SMEM1);
        cudaFuncSetAttribute(k_gemm3, cudaFuncAttributeMaxDynamicSharedMemorySize, SMEM1);
        attr_done = true;
    }

    __half *xqs, *xks, *wqs, *wvs;
    cudaGetSymbolAddress((void**)&xqs, g_XQs);
    cudaGetSymbolAddress((void**)&xks, g_XKs);
    cudaGetSymbolAddress((void**)&wqs, g_Wqs);
    cudaGetSymbolAddress((void**)&wvs, g_Wvs);

    // launch order: ncu (-s 5 -c 1) lands on launch #6 = k_gemm2
    k_round2<<<dim3((MM * DD / 4) / 256, 2), 256>>>(X_Q, X_KV, xqs, xks);  // #1
    k_round2<<<dim3((DD * DD / 4) / 256, 2), 256>>>(Wq, Wv, wqs, wvs);     // #2
    k_zero_qtv<<<1024, 256>>>();                                            // #3

    dim3 g1(DD / 256, MM / 128);          // (2, 256)
    k_gemm1<true> <<<g1, NT, SMEM1>>>(xqs, wqs, bq);                        // #4
    k_gemm1<false><<<g1, NT, SMEM1>>>(xks, wvs, bv);                        // #5

    dim3 g2(DD / 256, DD / 128, BB * 16); // (2, 4, 64)
    k_gemm2<<<g2, NT, SMEM1>>>();                                           // #6 <- ncu

    k_trans<<<dim3(16, 16, BB), dim3(32, 8)>>>();

    dim3 g3(DD / 256, MM / 128);          // (2, 256)
    k_gemm3<<<g3, NT, SMEM1>>>(gn_w, gn_b, out);

    k_tail<<<1, 1>>>(S_h, S_C, out, out_size);
}

// round 17
// speedup vs baseline: 1.6448x; 1.6448x over previous
#include <cuda_runtime.h>
#include <cuda_fp16.h>
#include <math.h>
#include <stdint.h>

#define DD 512
#define SS 8192
#define BB 4
#define MM (BB * SS)
#define GN_EPS 1e-6f
#define ROPE_L2 0.20762050593045702   // log2(10000)/64
#define NSPLIT 16

// CTA tile 128m x 128n, BK=32, pitch 80B rows. A(10240) B(10240)
#define STG1 20480
#define SMEM1 (3 * STG1)
#define NT 256

// ------------------------------------------------------------ device globals
__device__ __half g_XQs[(size_t)MM*DD];
__device__ __half g_XKs[(size_t)MM*DD];
__device__ __half g_Wqs[DD*DD], g_Wvs[DD*DD];
__device__ __half g_QTh[(size_t)DD*MM];
__device__ __half g_VTs[(size_t)DD*MM];
__device__ __half g_Kph[(size_t)MM*DD];
__device__ float  g_QtVp[(size_t)BB*NSPLIT*DD*DD];   // split-K partials
__device__ __half g_QtVTs[(size_t)BB*DD*DD];

// ------------------------------------------------------------------ helpers
__device__ __forceinline__ uint32_t smem_u32(const void* p) {
    uint32_t a;
    asm("{ .reg .u64 t; cvta.to.shared.u64 t, %1; cvt.u32.u64 %0, t; }" : "=r"(a) : "l"(p));
    return a;
}
#define CPA(dst, src) \
    asm volatile("cp.async.cg.shared.global [%0], [%1], 16;" :: "r"(dst), "l"(src) : "memory")
#define CPA_COMMIT() asm volatile("cp.async.commit_group;" ::: "memory")
#define CPA_WAIT(n)  asm volatile("cp.async.wait_group %0;" :: "n"(n) : "memory")
#define LDSM4(R, a) \
    asm volatile("ldmatrix.sync.aligned.m8n8.x4.shared.b16 {%0,%1,%2,%3}, [%4];" \
        : "=r"((R)[0]), "=r"((R)[1]), "=r"((R)[2]), "=r"((R)[3]) : "r"(a))

__device__ __forceinline__ void mma16816(float* d, const uint32_t* a, const uint32_t* b) {
    asm volatile("mma.sync.aligned.m16n8k16.row.col.f32.f16.f16.f32 "
        "{%0,%1,%2,%3},{%4,%5,%6,%7},{%8,%9},{%0,%1,%2,%3};"
        : "+f"(d[0]), "+f"(d[1]), "+f"(d[2]), "+f"(d[3])
        : "r"(a[0]), "r"(a[1]), "r"(a[2]), "r"(a[3]), "r"(b[0]), "r"(b[1]));
}

__device__ __forceinline__ float silu_f(float x) { return x / (1.0f + __expf(-x)); }

// load one stage: A, B tiles, 128 rows x 32 fp16 each, pitch 80B. 256 thr x 4 CPA
__device__ __forceinline__ void load_stage(const __half* A, const __half* B,
                                           size_t pa, size_t pb,
                                           int ar0, int br0, int kelem,
                                           uint32_t smst, int tid) {
    const int row = tid >> 1;
    const int cpair = (tid & 1) * 2;
#pragma unroll
    for (int i = 0; i < 2; i++) {
        const int c = cpair + i;
        const char* sA = (const char*)(A + (size_t)(ar0 + row) * pa + kelem) + c * 16;
        const char* sB = (const char*)(B + (size_t)(br0 + row) * pb + kelem) + c * 16;
        CPA(smst + row * 80 + c * 16, sA);
        CPA(smst + 10240 + row * 80 + c * 16, sB);
    }
}

// one BK=32 stage: warp tile 32m x 64n, single-term fp16
__device__ __forceinline__ void mma_stage(uint32_t smst, int wm, int wn, int lane,
                                          float acc[2][8][4]) {
#pragma unroll
    for (int kk = 0; kk < 2; kk++) {
        uint32_t a_addr = smst + (uint32_t)((wm * 32 + (lane & 15)) * 80 + kk * 32 + (lane >> 4) * 16);
        uint32_t ah[2][4];
        LDSM4(ah[0], a_addr);
        LDSM4(ah[1], a_addr + 16 * 80);
        uint32_t b_addr = smst + 10240 +
            (uint32_t)((wn * 64 + ((lane >> 4) << 3) + (lane & 7)) * 80 + kk * 32 + ((lane >> 3) & 1) * 16);
#pragma unroll
        for (int np = 0; np < 4; np++) {
            uint32_t bf[4];
            LDSM4(bf, b_addr + np * 16 * 80);
#pragma unroll
            for (int half = 0; half < 2; half++)
#pragma unroll
                for (int mi = 0; mi < 2; mi++)
                    mma16816(acc[mi][np * 2 + half], ah[mi], bf + half * 2);
        }
    }
}

__device__ __forceinline__ void run_gemm(const __half* A, const __half* B,
                                         size_t pa, size_t pb,
                                         int ar0, int br0, int kbase, int nstages,
                                         float acc[2][8][4], char* sm, int tid) {
#pragma unroll
    for (int mi = 0; mi < 2; mi++)
#pragma unroll
        for (int ni = 0; ni < 8; ni++)
#pragma unroll
            for (int j = 0; j < 4; j++) acc[mi][ni][j] = 0.f;

    uint32_t smb = smem_u32(sm);
    const int wid = tid >> 5;
    const int wm = wid >> 1, wn = wid & 1, lane = tid & 31;

    load_stage(A, B, pa, pb, ar0, br0, kbase, smb, tid);
    CPA_COMMIT();
    load_stage(A, B, pa, pb, ar0, br0, kbase + 32, smb + STG1, tid);
    CPA_COMMIT();

    for (int s = 0; s < nstages; s++) {
        if (s + 1 < nstages) { CPA_WAIT(1); } else { CPA_WAIT(0); }
        __syncthreads();
        if (s + 2 < nstages) {
            load_stage(A, B, pa, pb, ar0, br0, kbase + (s + 2) * 32,
                       smb + ((s + 2) % 3) * STG1, tid);
            CPA_COMMIT();
        }
        mma_stage(smb + (s % 3) * STG1, wm, wn, lane, acc);
    }
}

// =======================================================================
// GEMM1: Y = X@W^T + bias, rope(first 64 ch), silu.  single-term fp16.
// IS_Q: write QTh (transposed).  else: VTs (pre-rope) + Kph (row-major)
// grid (4, 256), 256 threads, 2 CTAs/SM
// =======================================================================
template<bool IS_Q>
__global__ __launch_bounds__(NT, 2) void k_gemm1(
    const __half* __restrict__ Xs, const __half* __restrict__ Ws,
    const float* __restrict__ bias)
{
    extern __shared__ char sm[];
    const int tid = threadIdx.x;
    const int row0 = blockIdx.y * 128, col0 = blockIdx.x * 128;
    float acc[2][8][4];
    run_gemm(Xs, Ws, DD, DD, row0, col0, 0, DD / 32, acc, sm, tid);

    const int lane = tid & 31, wid = tid >> 5;
    const int wm = wid >> 1, wn = wid & 1;
    const int cb = col0 + wn * 64 + (lane & 3) * 2;
    float b0[8], b1[8];
#pragma unroll
    for (int ni = 0; ni < 8; ni++) { b0[ni] = bias[cb + ni * 8]; b1[ni] = bias[cb + ni * 8 + 1]; }
    const bool ropew = (cb < 64);
    float invf[8];
    if (ropew) {
#pragma unroll
        for (int ni = 0; ni < 8; ni++)
            invf[ni] = (float)exp2(-(double)(cb + ni * 8) * ROPE_L2);
    }

#pragma unroll
    for (int mi = 0; mi < 2; mi++)
#pragma unroll
    for (int h = 0; h < 2; h++) {
        const int r = row0 + wm * 32 + mi * 16 + (lane >> 2) + h * 8;
        const float pos = (float)(r & (SS - 1));
#pragma unroll
        for (int ni = 0; ni < 8; ni++) {
            const int c = cb + ni * 8;
            float y0 = acc[mi][ni][h * 2 + 0] + b0[ni];
            float y1 = acc[mi][ni][h * 2 + 1] + b1[ni];
            if (!IS_Q) {   // V = silu(pre-rope), single fp16
                g_VTs[(size_t)c * MM + r]       = __float2half_rn(silu_f(y0));
                g_VTs[(size_t)(c + 1) * MM + r] = __float2half_rn(silu_f(y1));
            }
            if (ropew) {
                float sv, cv;
                sincosf(pos * invf[ni], &sv, &cv);
                float t0 = y0 * cv - y1 * sv;
                float t1 = y1 * cv + y0 * sv;
                y0 = t0; y1 = t1;
            }
            const __half s0 = __float2half_rn(silu_f(y0));
            const __half s1 = __float2half_rn(silu_f(y1));
            if (IS_Q) {
                g_QTh[(size_t)c * MM + r]       = s0;
                g_QTh[(size_t)(c + 1) * MM + r] = s1;
            } else {
                *(__half2*)&g_Kph[(size_t)r * DD + c] = __halves2half2(s0, s1);
            }
        }
    }
}

// =======================================================================
// GEMM2: partial[b][sp][d][e] = sum_{n in chunk} QTh[d][n] * VTs[e][n]
// split-K 16 x 512, plain stores (no atomics)
// grid (4, 4, 64), 256 threads
// =======================================================================
__global__ __launch_bounds__(NT, 2) void k_gemm2()
{
    extern __shared__ char sm[];
    const int tid = threadIdx.x;
    const int e0 = blockIdx.x * 128, d0 = blockIdx.y * 128;
    const int b = blockIdx.z >> 4, sp = blockIdx.z & 15;
    const int nbase = b * SS + sp * 512;
    float acc[2][8][4];
    run_gemm(g_QTh, g_VTs, MM, MM, d0, e0, nbase, 512 / 32, acc, sm, tid);

    const int lane = tid & 31, wid = tid >> 5;
    const int wm = wid >> 1, wn = wid & 1;
    const int cb = e0 + wn * 64 + (lane & 3) * 2;
    float* base = g_QtVp + (size_t)(b * NSPLIT + sp) * DD * DD;
#pragma unroll
    for (int mi = 0; mi < 2; mi++)
#pragma unroll
    for (int h = 0; h < 2; h++) {
        const int d = d0 + wm * 32 + mi * 16 + (lane >> 2) + h * 8;
#pragma unroll
        for (int ni = 0; ni < 8; ni++) {
            const int e = cb + ni * 8;
            *(float2*)(base + (size_t)d * DD + e) =
                make_float2(acc[mi][ni][h * 2 + 0], acc[mi][ni][h * 2 + 1]);
        }
    }
}

// =======================================================================
// GEMM3 + GroupNorm: out[r][e] = GN( sum_d Kph[r][d] * QtVTs[e][d] )
// grid (4, 256), 256 threads; warp owns one 64-ch group
// =======================================================================
__global__ __launch_bounds__(NT, 2) void k_gemm3(
    const float* __restrict__ gn_w, const float* __restrict__ gn_b,
    float* __restrict__ out)
{
    extern __shared__ char sm[];
    const int tid = threadIdx.x;
    const int row0 = blockIdx.y * 128, e0 = blockIdx.x * 128;
    const int b = row0 >> 13;
    float acc[2][8][4];
    run_gemm(g_Kph, g_QtVTs + (size_t)b * DD * DD, DD, DD, row0, e0, 0, DD / 32, acc, sm, tid);

    const int lane = tid & 31, wid = tid >> 5;
    const int wm = wid >> 1, wn = wid & 1;
    const int cb = e0 + wn * 64 + (lane & 3) * 2;

#pragma unroll
    for (int mi = 0; mi < 2; mi++)
#pragma unroll
    for (int h = 0; h < 2; h++) {
        const int r = row0 + wm * 32 + mi * 16 + (lane >> 2) + h * 8;
        float s = 0.f, q = 0.f;
#pragma unroll
        for (int ni = 0; ni < 8; ni++) {
            float v0 = acc[mi][ni][h * 2 + 0], v1 = acc[mi][ni][h * 2 + 1];
            s += v0 + v1;
            q += v0 * v0 + v1 * v1;
        }
        s += __shfl_xor_sync(0xffffffffu, s, 1);
        q += __shfl_xor_sync(0xffffffffu, q, 1);
        s += __shfl_xor_sync(0xffffffffu, s, 2);
        q += __shfl_xor_sync(0xffffffffu, q, 2);
        const float mean = s * (1.0f / 64.0f);
        const float var  = q * (1.0f / 64.0f) - mean * mean;
        const float rstd = rsqrtf(var + GN_EPS);
        float* orow = out + (size_t)r * DD;
#pragma unroll
        for (int ni = 0; ni < 8; ni++) {
            const int e = cb + ni * 8;
            float2 o;
            o.x = (acc[mi][ni][h * 2 + 0] - mean) * rstd * gn_w[e]     + gn_b[e];
            o.y = (acc[mi][ni][h * 2 + 1] - mean) * rstd * gn_w[e + 1] + gn_b[e + 1];
            *(float2*)(orow + e) = o;
        }
    }
}

// ---------------------------------------------------------- aux kernels
__global__ void k_round2(const float* __restrict__ srcA, const float* __restrict__ srcB,
                         __half* __restrict__ dA, __half* __restrict__ dB)
{
    const float* src = blockIdx.y ? srcB : srcA;
    __half* dst = blockIdx.y ? dB : dA;
    const int i = blockIdx.x * 256 + threadIdx.x;
    float4 v = ((const float4*)src)[i];
    ((__half2*)dst)[i * 2]     = __halves2half2(__float2half_rn(v.x), __float2half_rn(v.y));
    ((__half2*)dst)[i * 2 + 1] = __halves2half2(__float2half_rn(v.z), __float2half_rn(v.w));
}

// reduce 16 split-K partials + transpose + round -> QtVTs.  grid (16,16,4), block (32,8)
__global__ void k_trans() {
    __shared__ float t[32][33];
    const int b = blockIdx.z;
    const int d0 = blockIdx.y * 32, e0 = blockIdx.x * 32;
    const float* src = g_QtVp + (size_t)b * NSPLIT * DD * DD;
    __half* ds = g_QtVTs + (size_t)b * DD * DD;
    const int x = threadIdx.x, y0 = threadIdx.y;
#pragma unroll
    for (int i = 0; i < 32; i += 8) {
        float s = 0.f;
        const size_t off = (size_t)(d0 + y0 + i) * DD + e0 + x;
#pragma unroll
        for (int sp = 0; sp < NSPLIT; sp++)
            s += src[(size_t)sp * DD * DD + off];
        t[y0 + i][x] = s;
    }
    __syncthreads();
#pragma unroll
    for (int i = 0; i < 32; i += 8)
        ds[(size_t)(e0 + y0 + i) * DD + d0 + x] = __float2half_rn(t[x][y0 + i]);
}

__global__ void k_tail(const float* __restrict__ sh, const float* __restrict__ sc,
                       float* __restrict__ out, int out_size) {
    out[out_size - 2] = sh[0];
    out[out_size - 1] = sc[0];
}

// ---------------------------------------------------------------- launch
extern "C" void kernel_launch(void* const* d_in, const int* in_sizes, int n_in,
                              void* d_out, int out_size)
{
    (void)in_sizes; (void)n_in;
    const float* X_Q  = (const float*)d_in[0];
    const float* X_KV = (const float*)d_in[1];
    const float* S_h  = (const float*)d_in[2];
    const float* S_C  = (const float*)d_in[3];
    const float* Wq   = (const float*)d_in[4];
    const float* bq   = (const float*)d_in[5];
    const float* Wv   = (const float*)d_in[8];
    const float* bv   = (const float*)d_in[9];
    const float* gn_w = (const float*)d_in[10];
    const float* gn_b = (const float*)d_in[11];
    float* out = (float*)d_out;

    static bool attr_done = false;
    if (!attr_done) {
        cudaFuncSetAttribute(k_gemm1<true>,  cudaFuncAttributeMaxDynamicSharedMemorySize, SMEM1);
        cudaFuncSetAttribute(k_gemm1<false>, cudaFuncAttributeMaxDynamicSharedMemorySize, SMEM1);
        cudaFuncSetAttribute(k_gemm2, cudaFuncAttributeMaxDynamicSharedMemorySize, SMEM1);
        cudaFuncSetAttribute(k_gemm3, cudaFuncAttributeMaxDynamicSharedMemorySize, SMEM1);
        attr_done = true;
    }

    __half *xqs, *xks, *wqs, *wvs;
    cudaGetSymbolAddress((void**)&xqs, g_XQs);
    cudaGetSymbolAddress((void**)&xks, g_XKs);
    cudaGetSymbolAddress((void**)&wqs, g_Wqs);
    cudaGetSymbolAddress((void**)&wvs, g_Wvs);

    // launch order: ncu (-s 5 -c 1) lands on launch #6 = k_gemm2
    k_round2<<<dim3((MM * DD / 4) / 256, 2), 256>>>(X_Q, X_KV, xqs, xks);  // #1
    k_round2<<<dim3((DD * DD / 4) / 256, 2), 256>>>(Wq, Wv, wqs, wvs);     // #2

    dim3 g1(DD / 128, MM / 128);          // (4, 256)
    k_gemm1<true> <<<g1, NT, SMEM1>>>(xqs, wqs, bq);                        // #3
    k_gemm1<false><<<g1, NT, SMEM1>>>(xks, wvs, bv);                        // #4

    k_tail<<<1, 1>>>(S_h, S_C, out, out_size);                              // #5

    dim3 g2(DD / 128, DD / 128, BB * NSPLIT); // (4, 4, 64)
    k_gemm2<<<g2, NT, SMEM1>>>();                                           // #6 <- ncu

    k_trans<<<dim3(16, 16, BB), dim3(32, 8)>>>();                           // #7

    dim3 g3(DD / 128, MM / 128);          // (4, 256)
    k_gemm3<<<g3, NT, SMEM1>>>(gn_w, gn_b, out);                            // #8
}